// round 8
// baseline (speedup 1.0000x reference)
#include <cuda_runtime.h>

// ---------------------------------------------------------------------------
// MomGRU persistent recurrence, round 8 = R7 + pre-barrier local-K GEMM.
// Grid 128 CTAs = 32 batch-blocks x 4 hidden-blocks; cluster(4) per batch
// block; 256 threads. Thread tile 6 gate-rows x 4 batches, K split 8-way,
// reduce-scatter butterfly. NEW: each CTA's own h-slice (k-chunks 2j,2j+1)
// is kept in smem locally, so 25% of the GEMM runs in the shadow of the
// post-wait LDG of the peers' h. Exchange: stcg/ldcg + aligned cluster bar.
// ---------------------------------------------------------------------------

namespace {
constexpr int BATCH = 128;
constexpr int SEQ   = 1024;
constexpr int HID   = 256;
constexpr int GB    = 32;              // batch blocks
constexpr int GH    = 4;               // hidden blocks (= cluster size)
constexpr int NCTA  = GB * GH;         // 128
constexpr int BB    = BATCH / GB;      // 4 batches per CTA
constexpr int UPC   = HID / GH;        // 64 hidden units per CTA
constexpr int NROWS = 3 * UPC;         // 192 W_hh rows per CTA
constexpr int NTH   = 256;
constexpr int RSW   = HID + 16;        // 272 weight row stride (floats)
constexpr int RSH   = HID + 4;         // 260 h row stride (floats)

// smem layout (floats)
constexpr int OFF_W   = 0;                       // NROWS * RSW = 52224
constexpr int OFF_H   = OFF_W + NROWS * RSW;     // BB * RSH = 1040
constexpr int OFF_WBH = OFF_H + BB * RSH;        // HID
constexpr int OFF_WHD = OFF_WBH + HID;           // HID
constexpr int OFF_BS  = OFF_WHD + HID;           // BB
constexpr int OFF_XS  = OFF_BS + BB;             // BB float2
constexpr int SMEM_FLOATS = OFF_XS + BB * 2;
constexpr int SMEM_BYTES  = SMEM_FLOATS * 4;     // ~215.2 KB
}

// persistent h ping-pong, layout [buf][batch][hid]
__device__ float g_h[2][BATCH][HID];

// ---- packed fp32x2 helpers -------------------------------------------------
__device__ __forceinline__ unsigned long long pk2(float2 v) {
    unsigned long long r;
    asm("mov.b64 %0, {%1,%2};" : "=l"(r) : "f"(v.x), "f"(v.y));
    return r;
}
__device__ __forceinline__ float2 upk2(unsigned long long v) {
    float2 r;
    asm("mov.b64 {%0,%1}, %2;" : "=f"(r.x), "=f"(r.y) : "l"(v));
    return r;
}
__device__ __forceinline__ float2 ffma2(float2 a, float2 b, float2 c) {
    unsigned long long d;
    asm("fma.rn.f32x2 %0, %1, %2, %3;"
        : "=l"(d) : "l"(pk2(a)), "l"(pk2(b)), "l"(pk2(c)));
    return upk2(d);
}

__device__ __forceinline__ float sigf(float x) {
    return __fdividef(1.0f, 1.0f + __expf(-x));
}
__device__ __forceinline__ float tanh_fast(float x) {
    float ax = fabsf(x);
    float e  = __expf(-2.0f * ax);
    return copysignf(__fdividef(1.0f - e, 1.0f + e), x);
}

// Reduce-scatter over 8 ks lanes: v[8] = per-lane partial sums for slots 0..7;
// returns the full sum of slot 'ks' on lane with K-split index ks.
__device__ __forceinline__ float reduce_scatter8(const float v[8], int ks) {
    float w[4];
    #pragma unroll
    for (int i = 0; i < 4; ++i) {
        float mine  = (ks & 4) ? v[i + 4] : v[i];
        float their = (ks & 4) ? v[i]     : v[i + 4];
        w[i] = mine + __shfl_xor_sync(0xffffffffu, their, 4);
    }
    float y[2];
    #pragma unroll
    for (int i = 0; i < 2; ++i) {
        float mine  = (ks & 2) ? w[i + 2] : w[i];
        float their = (ks & 2) ? w[i]     : w[i + 2];
        y[i] = mine + __shfl_xor_sync(0xffffffffu, their, 2);
    }
    float mine  = (ks & 1) ? y[1] : y[0];
    float their = (ks & 1) ? y[0] : y[1];
    return mine + __shfl_xor_sync(0xffffffffu, their, 1);
}

#define CLUSTER_ARRIVE() asm volatile("barrier.cluster.arrive.aligned;" ::: "memory")
#define CLUSTER_WAIT()   asm volatile("barrier.cluster.wait.aligned;"   ::: "memory")

extern "C" __global__ void __launch_bounds__(NTH, 1) __cluster_dims__(GH, 1, 1)
momgru_kernel(const float* __restrict__ x,
              const float* __restrict__ W_ih,
              const float* __restrict__ W_hh,
              const float* __restrict__ b_ih,
              const float* __restrict__ b_hh,
              const float* __restrict__ Wb_x,
              const float* __restrict__ Wb_h,
              const float* __restrict__ b_beta,
              const float* __restrict__ s_ptr,
              const float* __restrict__ W_head,
              const float* __restrict__ b_head,
              float* __restrict__ out)
{
    extern __shared__ float sm[];
    float*  ws     = sm + OFF_W;
    float*  hs     = sm + OFF_H;
    float*  wbhs   = sm + OFF_WBH;
    float*  whds   = sm + OFF_WHD;
    float*  beta_s = sm + OFF_BS;
    float2* xs     = (float2*)(sm + OFF_XS);

    const int tid = threadIdx.x;
    const int j   = blockIdx.x & (GH - 1);    // hidden block / cluster rank
    const int i   = blockIdx.x >> 2;          // batch block
    const int b0  = i * BB;
    const int u0  = j * UPC;

    const int up = tid >> 3;        // 0..31  u-pair index
    const int ks = tid & 7;         // 0..7   K-split lane
    const int uo = up * 2 + (ks >> 2);   // owned local u (0..63)
    const int bo = ks & 3;               // owned local batch (0..3)

    // ---- one-time preload ----------------------------------------------------
    for (int e = tid; e < NROWS * HID; e += NTH) {
        int row = e >> 8;           // 0..191
        int k   = e & (HID - 1);
        int g   = row >> 6;         // gate
        int uu  = row & 63;
        ws[row * RSW + k] = W_hh[(g * HID + u0 + uu) * HID + k];
    }
    for (int e = tid; e < HID; e += NTH) {
        wbhs[e] = Wb_h[e];
        whds[e] = W_head[e];
    }
    // zero h staging (pre-GEMM at t=0 reads zeros from own region)
    for (int e = tid; e < BB * RSH; e += NTH) hs[e] = 0.0f;

    const float wbx0  = __ldg(Wb_x);
    const float wbx1  = __ldg(Wb_x + 1);
    const float bbeta = __ldg(b_beta);
    const float sv    = __ldg(s_ptr);
    const float bhead = __ldg(b_head);

    float2 wihg[3];
    float  bihg[3], bhhg[3];
    #pragma unroll
    for (int g = 0; g < 3; ++g) {
        int gr  = g * HID + u0 + uo;
        wihg[g] = make_float2(__ldg(W_ih + gr * 2), __ldg(W_ih + gr * 2 + 1));
        bihg[g] = __ldg(b_ih + gr);
        bhhg[g] = __ldg(b_hh + gr);
    }

    // zero h0 (each CTA zeroes a disjoint 256-float slice of buffer 0)
    {
        float* gz = &g_h[0][0][0];
        __stcg(gz + blockIdx.x * NTH + tid, 0.0f);
    }
    __syncthreads();    // hs zeros visible CTA-wide before first pre-GEMM
    CLUSTER_ARRIVE();   // release: h0 zeros visible at first wait

    // per-thread momentum state for (uo, bo)
    float v0 = 0.f, v1 = 0.f, v2 = 0.f;

    // weight row pointers: rows g*64 + 2*up + q
    const float* wp[3][2];
    #pragma unroll
    for (int g = 0; g < 3; ++g)
        #pragma unroll
        for (int q = 0; q < 2; ++q)
            wp[g][q] = ws + (g * UPC + up * 2 + q) * RSW + ks * 4;

    const float* hp[4];
    #pragma unroll
    for (int b = 0; b < 4; ++b)
        hp[b] = hs + b * RSH + ks * 4;

    const int bb = tid >> 4;        // beta batch (tid<64): 0..3
    const int kc = tid & 15;        // beta K-chunk lane

    for (int t = 0; t < SEQ; ++t) {
        // x prefetch BEFORE the wait (independent of peers' h)
        float2 xv = make_float2(0.f, 0.f);
        if (tid < 64 && kc == 0)
            xv = __ldg((const float2*)x + (b0 + bb) * SEQ + t);

        CLUSTER_WAIT();   // acquire: peers' h_t stores visible in L2

        // ---- issue LDG for the full h_t row block (latency hidden below) ----
        const float* hsrc = &g_h[t & 1][b0][0];
        float4 hv = __ldcg((const float4*)hsrc + tid);

        // accumulators for the whole K
        float2 acc[3][2][4];
        #pragma unroll
        for (int g = 0; g < 3; ++g)
            #pragma unroll
            for (int q = 0; q < 2; ++q)
                #pragma unroll
                for (int b = 0; b < 4; ++b) acc[g][q][b] = make_float2(0.f, 0.f);

        // GEMM chunk body (o = float offset within the k row)
        auto gemm_chunk = [&](int o) {
            float4 h4[4];
            #pragma unroll
            for (int b = 0; b < 4; ++b) h4[b] = *(const float4*)(hp[b] + o);
            #pragma unroll
            for (int g = 0; g < 3; ++g)
                #pragma unroll
                for (int q = 0; q < 2; ++q) {
                    float4 w4 = *(const float4*)(wp[g][q] + o);
                    float2 wa = make_float2(w4.x, w4.y);
                    float2 wb = make_float2(w4.z, w4.w);
                    #pragma unroll
                    for (int b = 0; b < 4; ++b) {
                        acc[g][q][b] = ffma2(wa, make_float2(h4[b].x, h4[b].y), acc[g][q][b]);
                        acc[g][q][b] = ffma2(wb, make_float2(h4[b].z, h4[b].w), acc[g][q][b]);
                    }
                }
        };

        // ---- pre-GEMM on OWN k-chunks {2j, 2j+1} (hs own region is local) ---
        // Runs in the shadow of the hv LDG. Benign race with other warps'
        // STS below: they write identical values into the own region.
        gemm_chunk((2 * j + 0) * 32);
        gemm_chunk((2 * j + 1) * 32);

        // ---- stage LDG result -> hs --------------------------------------------
        {
            int b = tid >> 6;
            int q = tid & 63;
            *(float4*)(hs + b * RSH + q * 4) = hv;
        }
        __syncthreads();

        // ---- beta: h . Wb_h (warps 0-1; 4 batches x 16 k-chunks) -------------
        if (tid < 64) {
            const float* hrow = hs + bb * RSH + kc * 4;
            const float* wrow = wbhs + kc * 4;
            float2 a2 = make_float2(0.f, 0.f);
            #pragma unroll
            for (int kk = 0; kk < 4; ++kk) {
                float4 h4 = *(const float4*)(hrow + kk * 64);
                float4 w4 = *(const float4*)(wrow + kk * 64);
                a2 = ffma2(make_float2(w4.x, w4.y), make_float2(h4.x, h4.y), a2);
                a2 = ffma2(make_float2(w4.z, w4.w), make_float2(h4.z, h4.w), a2);
            }
            float a = a2.x + a2.y;
            a += __shfl_xor_sync(0xffffffffu, a, 1);
            a += __shfl_xor_sync(0xffffffffu, a, 2);
            a += __shfl_xor_sync(0xffffffffu, a, 4);
            a += __shfl_xor_sync(0xffffffffu, a, 8);
            if (kc == 0) {
                float bval = sigf(xv.x * wbx0 + xv.y * wbx1 + a + bbeta);
                beta_s[bb] = bval;
                xs[bb]     = xv;
                if (j == 0) out[BATCH + (b0 + bb) * SEQ + t] = bval;
            }
        }

        // ---- main GEMM: remaining 6 chunks (skip own pair) -------------------
        #pragma unroll
        for (int kk = 0; kk < 8; ++kk) {
            if ((kk >> 1) == j) continue;     // uniform per CTA
            gemm_chunk(kk * 32);
        }

        // ---- reduce-scatter over ks lanes: thread keeps its own (uo,bo) ------
        float gh[3];
        #pragma unroll
        for (int g = 0; g < 3; ++g) {
            float v[8];
            #pragma unroll
            for (int q = 0; q < 2; ++q)
                #pragma unroll
                for (int b = 0; b < 4; ++b)
                    v[q * 4 + b] = acc[g][q][b].x + acc[g][q][b].y;
            gh[g] = reduce_scatter8(v, ks) + bhhg[g];
        }

        __syncthreads();   // beta_s / xs published; hs reads of step t done

        // ---- v update + gates: thread owns (uo, bo) --------------------------
        {
            const float  be    = beta_s[bo];
            const float2 xv2   = xs[bo];
            const float  hprev = hs[bo * RSH + u0 + uo];

            float pr = xv2.x * wihg[0].x + xv2.y * wihg[0].y + bihg[0];
            float pz = xv2.x * wihg[1].x + xv2.y * wihg[1].y + bihg[1];
            float pn = xv2.x * wihg[2].x + xv2.y * wihg[2].y + bihg[2];
            v0 = be * v0 + sv * pr;
            v1 = be * v1 + sv * pz;
            v2 = be * v2 + sv * pn;

            float r  = sigf(v0 + gh[0]);
            float z  = sigf(v1 + gh[1]);
            float n  = tanh_fast(v2 + r * gh[2]);
            float hn = (1.0f - z) * n + z * hprev;

            // own-region staging for next step's pre-GEMM + global publish
            hs[bo * RSH + u0 + uo] = hn;
            __stcg(&g_h[(t + 1) & 1][b0 + bo][u0 + uo], hn);
        }

        CLUSTER_ARRIVE();  // release h_{t+1} stores (per-thread release)
        __syncthreads();   // own-region hs stores visible before next pre-GEMM
    }

    CLUSTER_WAIT();        // final h_T (buffer 0) visible

    // ---- head: out[b] = h_T . W_head + b_head (rank-0 CTA per batch block) ---
    if (j == 0 && tid < 64) {
        int b = tid >> 4;
        const float* hT = &g_h[0][b0 + b][0];
        float2 a2 = make_float2(0.f, 0.f);
        #pragma unroll
        for (int kk = 0; kk < 4; ++kk) {
            float4 h4 = __ldcg((const float4*)(hT + kc * 4 + kk * 64));
            float4 w4 = *(const float4*)(whds + kc * 4 + kk * 64);
            a2 = ffma2(make_float2(w4.x, w4.y), make_float2(h4.x, h4.y), a2);
            a2 = ffma2(make_float2(w4.z, w4.w), make_float2(h4.z, h4.w), a2);
        }
        float a = a2.x + a2.y;
        a += __shfl_xor_sync(0xffffffffu, a, 1);
        a += __shfl_xor_sync(0xffffffffu, a, 2);
        a += __shfl_xor_sync(0xffffffffu, a, 4);
        a += __shfl_xor_sync(0xffffffffu, a, 8);
        if (kc == 0) out[b0 + b] = a + bhead;
    }
}

extern "C" void kernel_launch(void* const* d_in, const int* in_sizes, int n_in,
                              void* d_out, int out_size) {
    const float* x      = (const float*)d_in[0];
    const float* W_ih   = (const float*)d_in[1];
    const float* W_hh   = (const float*)d_in[2];
    const float* b_ih   = (const float*)d_in[3];
    const float* b_hh   = (const float*)d_in[4];
    const float* Wb_x   = (const float*)d_in[5];
    const float* Wb_h   = (const float*)d_in[6];
    const float* b_beta = (const float*)d_in[7];
    const float* s      = (const float*)d_in[8];
    const float* W_head = (const float*)d_in[9];
    const float* b_head = (const float*)d_in[10];

    cudaFuncSetAttribute(momgru_kernel,
                         cudaFuncAttributeMaxDynamicSharedMemorySize,
                         SMEM_BYTES);

    momgru_kernel<<<NCTA, NTH, SMEM_BYTES>>>(
        x, W_ih, W_hh, b_ih, b_hh, Wb_x, Wb_h, b_beta, s, W_head, b_head,
        (float*)d_out);
}

// round 9
// speedup vs baseline: 1.2520x; 1.2520x over previous
#include <cuda_runtime.h>

// ---------------------------------------------------------------------------
// MomGRU persistent recurrence, round 9 = R7 + static own-K pre-GEMM overlap.
// Grid 128 CTAs = 32 batch-blocks x 4 hidden-blocks; cluster(4); 256 threads.
// K-PERMUTED smem: W_hh / Wb_h / h staged rotated by -64*rank in k, so the
// CTA's own k-chunks are ALWAYS local chunks 0-1 (static offsets). Ping-pong
// smem h buffers let the pre-GEMM run before the post-wait LDG completes.
// Exchange: stcg/ldcg in L2 + aligned cluster barrier (R7-proven).
// ---------------------------------------------------------------------------

namespace {
constexpr int BATCH = 128;
constexpr int SEQ   = 1024;
constexpr int HID   = 256;
constexpr int GB    = 32;              // batch blocks
constexpr int GH    = 4;               // hidden blocks (= cluster size)
constexpr int NCTA  = GB * GH;         // 128
constexpr int BB    = BATCH / GB;      // 4 batches per CTA
constexpr int UPC   = HID / GH;        // 64 hidden units per CTA
constexpr int NROWS = 3 * UPC;         // 192 W_hh rows per CTA
constexpr int NTH   = 256;
constexpr int RSW   = HID + 16;        // 272 weight row stride (floats)
constexpr int RSH   = HID + 4;         // 260 h row stride (floats)
constexpr int HBUF  = BB * RSH;        // 1040 floats per h buffer

// smem layout (floats)
constexpr int OFF_W   = 0;                       // NROWS * RSW = 52224
constexpr int OFF_H   = OFF_W + NROWS * RSW;     // 2 * HBUF (ping-pong)
constexpr int OFF_WBH = OFF_H + 2 * HBUF;        // HID
constexpr int OFF_WHD = OFF_WBH + HID;           // HID
constexpr int OFF_BS  = OFF_WHD + HID;           // BB
constexpr int OFF_XS  = OFF_BS + BB;             // BB float2
constexpr int SMEM_FLOATS = OFF_XS + BB * 2;
constexpr int SMEM_BYTES  = SMEM_FLOATS * 4;     // ~219.4 KB
}

// persistent h ping-pong, layout [buf][batch][hid]
__device__ float g_h[2][BATCH][HID];

// ---- packed fp32x2 helpers -------------------------------------------------
__device__ __forceinline__ unsigned long long pk2(float2 v) {
    unsigned long long r;
    asm("mov.b64 %0, {%1,%2};" : "=l"(r) : "f"(v.x), "f"(v.y));
    return r;
}
__device__ __forceinline__ float2 upk2(unsigned long long v) {
    float2 r;
    asm("mov.b64 {%0,%1}, %2;" : "=f"(r.x), "=f"(r.y) : "l"(v));
    return r;
}
__device__ __forceinline__ float2 ffma2(float2 a, float2 b, float2 c) {
    unsigned long long d;
    asm("fma.rn.f32x2 %0, %1, %2, %3;"
        : "=l"(d) : "l"(pk2(a)), "l"(pk2(b)), "l"(pk2(c)));
    return upk2(d);
}

__device__ __forceinline__ float sigf(float x) {
    return __fdividef(1.0f, 1.0f + __expf(-x));
}
__device__ __forceinline__ float tanh_fast(float x) {
    float ax = fabsf(x);
    float e  = __expf(-2.0f * ax);
    return copysignf(__fdividef(1.0f - e, 1.0f + e), x);
}

// Reduce-scatter over 8 ks lanes (R7-proven).
__device__ __forceinline__ float reduce_scatter8(const float v[8], int ks) {
    float w[4];
    #pragma unroll
    for (int i = 0; i < 4; ++i) {
        float mine  = (ks & 4) ? v[i + 4] : v[i];
        float their = (ks & 4) ? v[i]     : v[i + 4];
        w[i] = mine + __shfl_xor_sync(0xffffffffu, their, 4);
    }
    float y[2];
    #pragma unroll
    for (int i = 0; i < 2; ++i) {
        float mine  = (ks & 2) ? w[i + 2] : w[i];
        float their = (ks & 2) ? w[i]     : w[i + 2];
        y[i] = mine + __shfl_xor_sync(0xffffffffu, their, 2);
    }
    float mine  = (ks & 1) ? y[1] : y[0];
    float their = (ks & 1) ? y[0] : y[1];
    return mine + __shfl_xor_sync(0xffffffffu, their, 1);
}

#define CLUSTER_ARRIVE() asm volatile("barrier.cluster.arrive.aligned;" ::: "memory")
#define CLUSTER_WAIT()   asm volatile("barrier.cluster.wait.aligned;"   ::: "memory")

extern "C" __global__ void __launch_bounds__(NTH, 1) __cluster_dims__(GH, 1, 1)
momgru_kernel(const float* __restrict__ x,
              const float* __restrict__ W_ih,
              const float* __restrict__ W_hh,
              const float* __restrict__ b_ih,
              const float* __restrict__ b_hh,
              const float* __restrict__ Wb_x,
              const float* __restrict__ Wb_h,
              const float* __restrict__ b_beta,
              const float* __restrict__ s_ptr,
              const float* __restrict__ W_head,
              const float* __restrict__ b_head,
              float* __restrict__ out)
{
    extern __shared__ float sm[];
    float*  ws     = sm + OFF_W;
    float*  hbuf   = sm + OFF_H;        // [2][BB][RSH], k-permuted
    float*  wbhs   = sm + OFF_WBH;      // k-permuted
    float*  whds   = sm + OFF_WHD;      // natural order (head reads g_h)
    float*  beta_s = sm + OFF_BS;
    float2* xs     = (float2*)(sm + OFF_XS);

    const int tid = threadIdx.x;
    const int j   = blockIdx.x & (GH - 1);    // hidden block / cluster rank
    const int i   = blockIdx.x >> 2;          // batch block
    const int b0  = i * BB;
    const int u0  = j * UPC;

    const int up = tid >> 3;        // 0..31  u-pair index
    const int ks = tid & 7;         // 0..7   K-split lane
    const int uo = up * 2 + (ks >> 2);   // owned local u (0..63)
    const int bo = ks & 3;               // owned local batch (0..3)

    // ---- one-time preload (k-permuted: kl = (k - u0) mod 256) ---------------
    for (int e = tid; e < NROWS * HID; e += NTH) {
        int row = e >> 8;           // 0..191
        int k   = e & (HID - 1);
        int g   = row >> 6;         // gate
        int uu  = row & 63;
        int kl  = (k - u0) & (HID - 1);
        ws[row * RSW + kl] = W_hh[(g * HID + u0 + uu) * HID + k];
    }
    for (int e = tid; e < HID; e += NTH) {
        wbhs[(e - u0) & (HID - 1)] = Wb_h[e];
        whds[e] = W_head[e];
    }
    // zero both h staging buffers (t=0 pre-GEMM reads zeros)
    for (int e = tid; e < 2 * HBUF; e += NTH) hbuf[e] = 0.0f;

    const float wbx0  = __ldg(Wb_x);
    const float wbx1  = __ldg(Wb_x + 1);
    const float bbeta = __ldg(b_beta);
    const float sv    = __ldg(s_ptr);
    const float bhead = __ldg(b_head);

    float2 wihg[3];
    float  bihg[3], bhhg[3];
    #pragma unroll
    for (int g = 0; g < 3; ++g) {
        int gr  = g * HID + u0 + uo;
        wihg[g] = make_float2(__ldg(W_ih + gr * 2), __ldg(W_ih + gr * 2 + 1));
        bihg[g] = __ldg(b_ih + gr);
        bhhg[g] = __ldg(b_hh + gr);
    }

    // zero h0 (each CTA zeroes a disjoint 256-float slice of buffer 0)
    {
        float* gz = &g_h[0][0][0];
        __stcg(gz + blockIdx.x * NTH + tid, 0.0f);
    }
    __syncthreads();    // smem zeros visible CTA-wide
    CLUSTER_ARRIVE();   // release: h0 zeros visible at first wait

    // per-thread momentum state for (uo, bo)
    float v0 = 0.f, v1 = 0.f, v2 = 0.f;

    // weight row pointers (k-permuted base + ks lane offset)
    const float* wp[3][2];
    #pragma unroll
    for (int g = 0; g < 3; ++g)
        #pragma unroll
        for (int q = 0; q < 2; ++q)
            wp[g][q] = ws + (g * UPC + up * 2 + q) * RSW + ks * 4;

    // staging permutation for this thread's LDG slot
    const int sb  = tid >> 6;                       // batch row
    const int skl = (((tid & 63) * 4) - u0) & (HID - 1);  // permuted k position

    const int bb = tid >> 4;        // beta batch (tid<64): 0..3
    const int kc = tid & 15;        // beta K-chunk lane

    for (int t = 0; t < SEQ; ++t) {
        float* hcur = hbuf + (t & 1) * HBUF;
        float* hnxt = hbuf + ((t + 1) & 1) * HBUF;

        // x prefetch BEFORE the wait (independent of peers' h)
        float2 xv = make_float2(0.f, 0.f);
        if (tid < 64 && kc == 0)
            xv = __ldg((const float2*)x + (b0 + bb) * SEQ + t);

        CLUSTER_WAIT();   // acquire: peers' h_t stores visible in L2

        // ---- issue LDG for the full h_t row block (consumed after pre-GEMM) --
        const float* hsrc = &g_h[t & 1][b0][0];
        float4 hv = __ldcg((const float4*)hsrc + tid);

        float2 acc[3][2][4];
        #pragma unroll
        for (int g = 0; g < 3; ++g)
            #pragma unroll
            for (int q = 0; q < 2; ++q)
                #pragma unroll
                for (int b = 0; b < 4; ++b) acc[g][q][b] = make_float2(0.f, 0.f);

        // ---- pre-GEMM: OWN k = local chunks 0..1 (static offsets) -----------
        // hcur own region written by gates at t-1 (visible via trailing sync).
        #pragma unroll
        for (int kk = 0; kk < 2; ++kk) {
            const int o = kk * 32;
            float4 h4[4];
            #pragma unroll
            for (int b = 0; b < 4; ++b)
                h4[b] = *(const float4*)(hcur + b * RSH + ks * 4 + o);
            #pragma unroll
            for (int g = 0; g < 3; ++g)
                #pragma unroll
                for (int q = 0; q < 2; ++q) {
                    float4 w4 = *(const float4*)(wp[g][q] + o);
                    float2 wa = make_float2(w4.x, w4.y);
                    float2 wb = make_float2(w4.z, w4.w);
                    #pragma unroll
                    for (int b = 0; b < 4; ++b) {
                        acc[g][q][b] = ffma2(wa, make_float2(h4[b].x, h4[b].y), acc[g][q][b]);
                        acc[g][q][b] = ffma2(wb, make_float2(h4[b].z, h4[b].w), acc[g][q][b]);
                    }
                }
        }

        // ---- stage LDG result into hcur at permuted position -----------------
        // Own region gets identical values (benign, R8-validated).
        *(float4*)(hcur + sb * RSH + skl) = hv;
        __syncthreads();

        // ---- beta: h . Wb_h (warps 0-1; permuted order, same dot product) ----
        if (tid < 64) {
            const float* hrow = hcur + bb * RSH + kc * 4;
            const float* wrow = wbhs + kc * 4;
            float2 a2 = make_float2(0.f, 0.f);
            #pragma unroll
            for (int kk = 0; kk < 4; ++kk) {
                float4 h4 = *(const float4*)(hrow + kk * 64);
                float4 w4 = *(const float4*)(wrow + kk * 64);
                a2 = ffma2(make_float2(w4.x, w4.y), make_float2(h4.x, h4.y), a2);
                a2 = ffma2(make_float2(w4.z, w4.w), make_float2(h4.z, h4.w), a2);
            }
            float a = a2.x + a2.y;
            a += __shfl_xor_sync(0xffffffffu, a, 1);
            a += __shfl_xor_sync(0xffffffffu, a, 2);
            a += __shfl_xor_sync(0xffffffffu, a, 4);
            a += __shfl_xor_sync(0xffffffffu, a, 8);
            if (kc == 0) {
                float bval = sigf(xv.x * wbx0 + xv.y * wbx1 + a + bbeta);
                beta_s[bb] = bval;
                xs[bb]     = xv;
                if (j == 0) out[BATCH + (b0 + bb) * SEQ + t] = bval;
            }
        }

        // ---- main GEMM: local chunks 2..7 (static unrolled loop) -------------
        #pragma unroll
        for (int kk = 2; kk < 8; ++kk) {
            const int o = kk * 32;
            float4 h4[4];
            #pragma unroll
            for (int b = 0; b < 4; ++b)
                h4[b] = *(const float4*)(hcur + b * RSH + ks * 4 + o);
            #pragma unroll
            for (int g = 0; g < 3; ++g)
                #pragma unroll
                for (int q = 0; q < 2; ++q) {
                    float4 w4 = *(const float4*)(wp[g][q] + o);
                    float2 wa = make_float2(w4.x, w4.y);
                    float2 wb = make_float2(w4.z, w4.w);
                    #pragma unroll
                    for (int b = 0; b < 4; ++b) {
                        acc[g][q][b] = ffma2(wa, make_float2(h4[b].x, h4[b].y), acc[g][q][b]);
                        acc[g][q][b] = ffma2(wb, make_float2(h4[b].z, h4[b].w), acc[g][q][b]);
                    }
                }
        }

        // ---- reduce-scatter over ks lanes: thread keeps its own (uo,bo) ------
        float gh[3];
        #pragma unroll
        for (int g = 0; g < 3; ++g) {
            float v[8];
            #pragma unroll
            for (int q = 0; q < 2; ++q)
                #pragma unroll
                for (int b = 0; b < 4; ++b)
                    v[q * 4 + b] = acc[g][q][b].x + acc[g][q][b].y;
            gh[g] = reduce_scatter8(v, ks) + bhhg[g];
        }

        __syncthreads();   // beta_s / xs published; all hcur reads done

        // ---- v update + gates: thread owns (uo, bo) --------------------------
        {
            const float  be    = beta_s[bo];
            const float2 xv2   = xs[bo];
            const float  hprev = hcur[bo * RSH + uo];   // permuted: own u at kl=uo

            float pr = xv2.x * wihg[0].x + xv2.y * wihg[0].y + bihg[0];
            float pz = xv2.x * wihg[1].x + xv2.y * wihg[1].y + bihg[1];
            float pn = xv2.x * wihg[2].x + xv2.y * wihg[2].y + bihg[2];
            v0 = be * v0 + sv * pr;
            v1 = be * v1 + sv * pz;
            v2 = be * v2 + sv * pn;

            float r  = sigf(v0 + gh[0]);
            float z  = sigf(v1 + gh[1]);
            float n  = tanh_fast(v2 + r * gh[2]);
            float hn = (1.0f - z) * n + z * hprev;

            hnxt[bo * RSH + uo] = hn;                   // next step's pre-GEMM
            __stcg(&g_h[(t + 1) & 1][b0 + bo][u0 + uo], hn);
        }

        CLUSTER_ARRIVE();  // release h_{t+1} stores
        __syncthreads();   // hnxt own-region visible before next pre-GEMM
    }

    CLUSTER_WAIT();        // final h_T (buffer 0) visible

    // ---- head: out[b] = h_T . W_head + b_head (rank-0 CTA per batch block) ---
    if (j == 0 && tid < 64) {
        int b = tid >> 4;
        const float* hT = &g_h[0][b0 + b][0];
        float2 a2 = make_float2(0.f, 0.f);
        #pragma unroll
        for (int kk = 0; kk < 4; ++kk) {
            float4 h4 = __ldcg((const float4*)(hT + kc * 4 + kk * 64));
            float4 w4 = *(const float4*)(whds + kc * 4 + kk * 64);
            a2 = ffma2(make_float2(w4.x, w4.y), make_float2(h4.x, h4.y), a2);
            a2 = ffma2(make_float2(w4.z, w4.w), make_float2(h4.z, h4.w), a2);
        }
        float a = a2.x + a2.y;
        a += __shfl_xor_sync(0xffffffffu, a, 1);
        a += __shfl_xor_sync(0xffffffffu, a, 2);
        a += __shfl_xor_sync(0xffffffffu, a, 4);
        a += __shfl_xor_sync(0xffffffffu, a, 8);
        if (kc == 0) out[b0 + b] = a + bhead;
    }
}

extern "C" void kernel_launch(void* const* d_in, const int* in_sizes, int n_in,
                              void* d_out, int out_size) {
    const float* x      = (const float*)d_in[0];
    const float* W_ih   = (const float*)d_in[1];
    const float* W_hh   = (const float*)d_in[2];
    const float* b_ih   = (const float*)d_in[3];
    const float* b_hh   = (const float*)d_in[4];
    const float* Wb_x   = (const float*)d_in[5];
    const float* Wb_h   = (const float*)d_in[6];
    const float* b_beta = (const float*)d_in[7];
    const float* s      = (const float*)d_in[8];
    const float* W_head = (const float*)d_in[9];
    const float* b_head = (const float*)d_in[10];

    cudaFuncSetAttribute(momgru_kernel,
                         cudaFuncAttributeMaxDynamicSharedMemorySize,
                         SMEM_BYTES);

    momgru_kernel<<<NCTA, NTH, SMEM_BYTES>>>(
        x, W_ih, W_hh, b_ih, b_hh, Wb_x, Wb_h, b_beta, s, W_head, b_head,
        (float*)d_out);
}